// round 10
// baseline (speedup 1.0000x reference)
#include <cuda_runtime.h>
#include <cuda_fp16.h>
#include <cstdint>
#include <math.h>

#define NHW 1024
#define KDIM 256
#define NBT 64

// ---------------- scratch (device globals: allocation-guard-safe) -------------
__device__ __half g_qkv[(size_t)NBT * 768 * NHW];   // 96 MB  [bt][768][hw]
__device__ __half g_att[(size_t)NBT * NHW * 256];   // 32 MB  [bt][hw][256]
__device__ __half g_xh [(size_t)NBT * KDIM * NHW];  // 32 MB  [bt][k][hw]
__device__ __half g_wh [(size_t)(768 + 256) * KDIM];

// ---------------- helpers ------------------------------------------------------
__device__ __forceinline__ uint32_t smem_u32(const void* p) {
    uint32_t a;
    asm("{ .reg .u64 t; cvta.to.shared.u64 t, %1; cvt.u32.u64 %0, t; }" : "=r"(a) : "l"(p));
    return a;
}
__device__ __forceinline__ uint32_t packh2(float lo, float hi) {
    __half2 h = __floats2half2_rn(lo, hi);
    return *reinterpret_cast<uint32_t*>(&h);
}
__device__ __forceinline__ uint32_t prmt(uint32_t a, uint32_t b, uint32_t sel) {
    uint32_t r;
    asm("prmt.b32 %0, %1, %2, %3;" : "=r"(r) : "r"(a), "r"(b), "r"(sel));
    return r;
}
__device__ __forceinline__ void cpa16(uint32_t dst, const void* src) {
    asm volatile("cp.async.cg.shared.global [%0], [%1], 16;" :: "r"(dst), "l"(src));
}
__device__ __forceinline__ void cpa_commit() { asm volatile("cp.async.commit_group;"); }
template<int N> __device__ __forceinline__ void cpa_wait() {
    asm volatile("cp.async.wait_group %0;" :: "n"(N));
}
#define LDSM_X4(r0, r1, r2, r3, addr) \
    asm volatile("ldmatrix.sync.aligned.m8n8.x4.shared.b16 {%0,%1,%2,%3}, [%4];" \
                 : "=r"(r0), "=r"(r1), "=r"(r2), "=r"(r3) : "r"(addr))
#define LDSM_X4_T(r0, r1, r2, r3, addr) \
    asm volatile("ldmatrix.sync.aligned.m8n8.x4.trans.shared.b16 {%0,%1,%2,%3}, [%4];" \
                 : "=r"(r0), "=r"(r1), "=r"(r2), "=r"(r3) : "r"(addr))
#define MMA16816(c, a, b0v, b1v) \
    asm volatile("mma.sync.aligned.m16n8k16.row.col.f32.f16.f16.f32 " \
                 "{%0,%1,%2,%3}, {%4,%5,%6,%7}, {%8,%9}, {%0,%1,%2,%3};" \
                 : "+f"((c)[0]), "+f"((c)[1]), "+f"((c)[2]), "+f"((c)[3]) \
                 : "r"((a)[0]), "r"((a)[1]), "r"((a)[2]), "r"((a)[3]), "r"(b0v), "r"(b1v))

// ---------------- tiny convert kernels -----------------------------------------
__global__ __launch_bounds__(256) void cvt_x_kernel(const float* __restrict__ x,
                                                    __half* __restrict__ xh) {
    const size_t i = ((size_t)blockIdx.x * 256 + threadIdx.x) * 4;
    float4 f = *(const float4*)(x + i);
    uint2 u;
    u.x = packh2(f.x, f.y); u.y = packh2(f.z, f.w);
    *(uint2*)(xh + i) = u;
}
__global__ __launch_bounds__(256) void cvt_w_kernel(const float* __restrict__ wq,
                                                    const float* __restrict__ wo,
                                                    __half* __restrict__ wh) {
    const size_t i = ((size_t)blockIdx.x * 256 + threadIdx.x) * 4;
    const float* src = (i < (size_t)768 * KDIM) ? (wq + i) : (wo + (i - (size_t)768 * KDIM));
    float4 f = *(const float4*)src;
    uint2 u;
    u.x = packh2(f.x, f.y); u.y = packh2(f.z, f.w);
    *(uint2*)(wh + i) = u;
}

// ---------------- GEMM: full-K resident, barrier-free mainloop -----------------
// C[bt][m][n] = sum_k A[m][k] * B_bt[k][n] + bias[m]
// smem: B full-K 64KB @0 ; A double buffer full-K 2 x 64KB @65536.
// MODE 0: B src g_xh [bt][k][n], smem [k][n] rows 256B, ldmatrix.trans; out fp16
// MODE 1: B src g_att [bt][n][k], smem [n][k] rows 512B, ldmatrix;      out fp32
#define FK_SMEM (65536 * 3)

template<int M, int MODE>
__global__ __launch_bounds__(512, 1) void gemm_fk_kernel(
    const __half* __restrict__ A, const __half* __restrict__ B,
    const float* __restrict__ bias, void* __restrict__ outv)
{
    extern __shared__ char smem[];
    const uint32_t sb = smem_u32(smem);

    const int tid  = threadIdx.x;
    const int lane = tid & 31;
    const int wid  = tid >> 5;
    const int wm   = wid >> 2;      // 0..3, 32 rows
    const int wn   = wid & 3;       // 0..3, 32 cols
    const int g8   = lane >> 2;
    const int t4   = lane & 3;

    const int bt = blockIdx.y;
    const int n0 = blockIdx.x * 128;

    const __half* Bb = (MODE == 0) ? (B + (size_t)bt * KDIM * NHW)
                                   : (B + (size_t)bt * NHW * KDIM);

    // ---- staging: A m-tile full-K (rows 512B, swizzled 16B cols) ----
    auto stage_A = [&](int buf, int m0) {
        const int m   = tid >> 2;
        const int kq0 = (tid & 3) * 8;
        const uint32_t dbase = sb + 65536u + (uint32_t)buf * 65536u + (uint32_t)m * 512u;
        const __half* src = A + (size_t)(m0 + m) * KDIM + kq0 * 8;
        #pragma unroll
        for (int q = 0; q < 8; q++) {
            const int k16 = kq0 + q;
            cpa16(dbase + (((uint32_t)k16 * 16u) ^ (((uint32_t)m & 7u) << 4)), src + q * 8);
        }
    };
    // ---- staging: B k-chunk kc (quarter of K) ----
    auto stage_Bc = [&](int kc) {
        if (MODE == 0) {
            const int k    = kc * 64 + (tid >> 3);
            const int n16b = (tid & 7) * 2;
            const uint32_t dbase = sb + (uint32_t)k * 256u;
            const __half* src = Bb + (size_t)k * NHW + n0;
            #pragma unroll
            for (int q = 0; q < 2; q++) {
                const int n16 = n16b + q;
                cpa16(dbase + (((uint32_t)n16 * 16u) ^ (((uint32_t)k & 7u) << 4)), src + n16 * 8);
            }
        } else {
            const int n  = tid >> 2;
            const int kb = kc * 8 + (tid & 3) * 2;
            const uint32_t dbase = sb + (uint32_t)n * 512u;
            const __half* src = Bb + (size_t)(n0 + n) * KDIM;
            #pragma unroll
            for (int q = 0; q < 2; q++) {
                const int k16 = kb + q;
                cpa16(dbase + (((uint32_t)k16 * 16u) ^ (((uint32_t)n & 7u) << 4)), src + k16 * 8);
            }
        }
    };

    // prologue: A0 | B0 B1 B2 B3 | A1  -> groups g0..g5
    stage_A(0, 0);   cpa_commit();
    stage_Bc(0);     cpa_commit();
    stage_Bc(1);     cpa_commit();
    stage_Bc(2);     cpa_commit();
    stage_Bc(3);     cpa_commit();
    stage_A(1, 128); cpa_commit();

    // fragment lane geometry (identical identities to prior rounds)
    const int am  = ((lane >> 3) & 1) * 8 + (lane & 7);
    const uint32_t aC = ((lane >> 4) & 1) * 16;
    const uint32_t aS = (uint32_t)(am & 7) << 4;
    const int bnl = ((lane >> 4) & 1) * 8 + (lane & 7);
    const uint32_t bC = ((lane >> 3) & 1) * 16;
    const uint32_t bS = (uint32_t)(bnl & 7) << 4;
    const int tk  = lane & 15;
    const int nc8 = ((lane >> 4) & 1) * 8;
    const uint32_t tS = ((uint32_t)lane & 7u) << 4;

    constexpr int MT = M / 128;
    for (int mt = 0; mt < MT; mt++) {
        const int m0 = mt * 128;
        const uint32_t abase = sb + 65536u + (uint32_t)(mt & 1) * 65536u;

        float acc[2][4][4];
        #pragma unroll
        for (int i = 0; i < 2; i++)
            #pragma unroll
            for (int j = 0; j < 4; j++)
                #pragma unroll
                for (int c = 0; c < 4; c++) acc[i][j][c] = 0.f;

        auto do_kk = [&](int kk) {
            uint32_t a[2][4], b[2][4];
            #pragma unroll
            for (int mf = 0; mf < 2; mf++)
                LDSM_X4(a[mf][0], a[mf][1], a[mf][2], a[mf][3],
                        abase + (uint32_t)(wm * 32 + mf * 16 + am) * 512u
                              + (((uint32_t)(kk * 32) + aC) ^ aS));
            #pragma unroll
            for (int nfp = 0; nfp < 2; nfp++) {
                if (MODE == 0) {
                    LDSM_X4_T(b[nfp][0], b[nfp][1], b[nfp][2], b[nfp][3],
                              sb + (uint32_t)((kk * 16 + tk) * 256)
                                 + (((uint32_t)((wn * 32 + nfp * 16 + nc8) * 2)) ^ tS));
                } else {
                    LDSM_X4(b[nfp][0], b[nfp][1], b[nfp][2], b[nfp][3],
                            sb + (uint32_t)((wn * 32 + nfp * 16 + bnl) * 512)
                               + (((uint32_t)(kk * 32) + bC) ^ bS));
                }
            }
            #pragma unroll
            for (int mf = 0; mf < 2; mf++)
                #pragma unroll
                for (int nf = 0; nf < 4; nf++)
                    MMA16816(acc[mf][nf], a[mf],
                             b[nf >> 1][(nf & 1) * 2], b[nf >> 1][(nf & 1) * 2 + 1]);
        };

        if (mt == 0) {
            // consume B chunk-by-chunk as it lands
            #pragma unroll
            for (int kc = 0; kc < 4; kc++) {
                switch (kc) {
                    case 0: cpa_wait<4>(); break;
                    case 1: cpa_wait<3>(); break;
                    case 2: cpa_wait<2>(); break;
                    default: cpa_wait<1>(); break;
                }
                __syncthreads();
                #pragma unroll
                for (int kk = kc * 4; kk < kc * 4 + 4; kk++) do_kk(kk);
            }
        } else {
            cpa_wait<1>();
            __syncthreads();
            #pragma unroll
            for (int kk = 0; kk < 16; kk++) do_kk(kk);
        }

        // ---- epilogue ----
        #pragma unroll
        for (int mf = 0; mf < 2; mf++) {
            const int m = m0 + wm * 32 + mf * 16 + g8;
            const float bz0 = bias[m], bz1 = bias[m + 8];
            #pragma unroll
            for (int nf = 0; nf < 4; nf++) {
                const int n = n0 + wn * 32 + nf * 8 + 2 * t4;
                if (MODE == 0) {
                    __half* Oh = (__half*)outv + (size_t)bt * M * NHW;
                    *(__half2*)(Oh + (size_t)m * NHW + n) =
                        __floats2half2_rn(acc[mf][nf][0] + bz0, acc[mf][nf][1] + bz0);
                    *(__half2*)(Oh + (size_t)(m + 8) * NHW + n) =
                        __floats2half2_rn(acc[mf][nf][2] + bz1, acc[mf][nf][3] + bz1);
                } else {
                    float* Of = (float*)outv + (size_t)bt * M * NHW;
                    *(float2*)(Of + (size_t)m * NHW + n) =
                        make_float2(acc[mf][nf][0] + bz0, acc[mf][nf][1] + bz0);
                    *(float2*)(Of + (size_t)(m + 8) * NHW + n) =
                        make_float2(acc[mf][nf][2] + bz1, acc[mf][nf][3] + bz1);
                }
            }
        }

        __syncthreads();                       // all reads of buf (mt&1) done
        if (mt + 2 < MT) stage_A(mt & 1, (mt + 2) * 128);
        cpa_commit();                          // commit (possibly empty) keeps counts
    }
}

// ---------------- temporal attention via tensor cores (R9, unchanged) ----------
#define AI_STRIDE 40
#define AI_Q 0
#define AI_K 1280
#define AI_V 2560
#define AI_BYTES 5120
#define ATT_REL_OFF (16 * AI_BYTES)
#define ATT_SMEM (ATT_REL_OFF + 1024)

__device__ __forceinline__ void htr8x8(const uint4* in, uint4* out) {
    const uint32_t* w = (const uint32_t*)in;
    #pragma unroll
    for (int t = 0; t < 8; t++) {
        const uint32_t sel = (t & 1) ? 0x7632u : 0x5410u;
        const int c = t >> 1;
        out[t].x = prmt(w[0 * 4 + c], w[1 * 4 + c], sel);
        out[t].y = prmt(w[2 * 4 + c], w[3 * 4 + c], sel);
        out[t].z = prmt(w[4 * 4 + c], w[5 * 4 + c], sel);
        out[t].w = prmt(w[6 * 4 + c], w[7 * 4 + c], sel);
    }
}

__global__ __launch_bounds__(512, 2) void attn_mma_kernel(
    const __half* __restrict__ qkv, const float* __restrict__ rel,
    __half* __restrict__ att)
{
    extern __shared__ char asmem[];
    const uint32_t sb = smem_u32(asmem);

    const int tid  = threadIdx.x;
    const int hw0  = blockIdx.x * 16;
    const int head = blockIdx.y;
    const int b    = blockIdx.z;
    const int bt0  = b * 16;

    if (tid >= 256) ((float*)(asmem + ATT_REL_OFF))[tid - 256] = rel[head * 256 + tid - 256];

    if (tid < 384) {
        uint4 in[8], out[8];
        if (tid < 256) {
            const int h8 = tid & 1;
            const int d8 = (tid >> 1) & 3;
            const int j  = (tid >> 3) & 15;
            const int tz = tid >> 7;
            const __half* src = qkv + ((size_t)(bt0 + j) * 768 + tz * 256 + head * 32 + d8 * 8) * NHW
                              + hw0 + h8 * 8;
            #pragma unroll
            for (int dd = 0; dd < 8; dd++)
                in[dd] = *(const uint4*)(src + (size_t)dd * NHW);
            htr8x8(in, out);
            const uint32_t dbase = sb + (uint32_t)tz * 1280u + (uint32_t)j * (AI_STRIDE * 2)
                                 + (uint32_t)d8 * 16u + (uint32_t)(h8 * 8) * AI_BYTES;
            #pragma unroll
            for (int t = 0; t < 8; t++)
                *(uint4*)(asmem + (dbase - sb) + (uint32_t)t * AI_BYTES) = out[t];
        } else {
            const int v  = tid - 256;
            const int h8 = v & 1;
            const int j8 = (v >> 1) & 1;
            const int d  = (v >> 2) & 31;
            const __half* src = qkv + ((size_t)(bt0 + j8 * 8) * 768 + 512 + head * 32 + d) * NHW
                              + hw0 + h8 * 8;
            #pragma unroll
            for (int jj = 0; jj < 8; jj++)
                in[jj] = *(const uint4*)(src + (size_t)jj * 768 * NHW);
            htr8x8(in, out);
            const uint32_t dbase = sb + AI_V + (uint32_t)d * (AI_STRIDE * 2)
                                 + (uint32_t)j8 * 16u + (uint32_t)(h8 * 8) * AI_BYTES;
            #pragma unroll
            for (int t = 0; t < 8; t++)
                *(uint4*)(asmem + (dbase - sb) + (uint32_t)t * AI_BYTES) = out[t];
        }
    }
    __syncthreads();

    const int w    = tid >> 5;
    const int lane = tid & 31;
    const int g8   = lane >> 2;
    const int t4   = lane & 3;
    const uint32_t ibase = sb + (uint32_t)w * AI_BYTES;

    const int am  = ((lane >> 3) & 1) * 8 + (lane & 7);
    const uint32_t aC = ((lane >> 4) & 1) * 16;
    const int bnl = ((lane >> 4) & 1) * 8 + (lane & 7);
    const uint32_t bC = ((lane >> 3) & 1) * 16;

    float S[2][4] = {{0.f, 0.f, 0.f, 0.f}, {0.f, 0.f, 0.f, 0.f}};
    #pragma unroll
    for (int kd = 0; kd < 2; kd++) {
        uint32_t aQ[4], bK[4];
        LDSM_X4(aQ[0], aQ[1], aQ[2], aQ[3],
                ibase + AI_Q + (uint32_t)am * (AI_STRIDE * 2) + aC + kd * 32);
        LDSM_X4(bK[0], bK[1], bK[2], bK[3],
                ibase + AI_K + (uint32_t)bnl * (AI_STRIDE * 2) + bC + kd * 32);
        MMA16816(S[0], aQ, bK[0], bK[1]);
        MMA16816(S[1], aQ, bK[2], bK[3]);
    }

    const float scale = 0.1767766952966369f;
    const float* relS = (const float*)(asmem + ATT_REL_OFF);
    float s[2][4];
    #pragma unroll
    for (int ng = 0; ng < 2; ng++)
        #pragma unroll
        for (int q = 0; q < 4; q++) {
            const int row = g8 + (q >= 2 ? 8 : 0);
            const int col = ng * 8 + 2 * t4 + (q & 1);
            s[ng][q] = S[ng][q] * scale + relS[row * 16 + col];
        }
    float mx0 = fmaxf(fmaxf(s[0][0], s[0][1]), fmaxf(s[1][0], s[1][1]));
    float mx8 = fmaxf(fmaxf(s[0][2], s[0][3]), fmaxf(s[1][2], s[1][3]));
    mx0 = fmaxf(mx0, __shfl_xor_sync(0xFFFFFFFFu, mx0, 1));
    mx0 = fmaxf(mx0, __shfl_xor_sync(0xFFFFFFFFu, mx0, 2));
    mx8 = fmaxf(mx8, __shfl_xor_sync(0xFFFFFFFFu, mx8, 1));
    mx8 = fmaxf(mx8, __shfl_xor_sync(0xFFFFFFFFu, mx8, 2));
    #pragma unroll
    for (int ng = 0; ng < 2; ng++) {
        s[ng][0] = __expf(s[ng][0] - mx0);
        s[ng][1] = __expf(s[ng][1] - mx0);
        s[ng][2] = __expf(s[ng][2] - mx8);
        s[ng][3] = __expf(s[ng][3] - mx8);
    }
    float l0 = s[0][0] + s[0][1] + s[1][0] + s[1][1];
    float l8 = s[0][2] + s[0][3] + s[1][2] + s[1][3];
    l0 += __shfl_xor_sync(0xFFFFFFFFu, l0, 1);
    l0 += __shfl_xor_sync(0xFFFFFFFFu, l0, 2);
    l8 += __shfl_xor_sync(0xFFFFFFFFu, l8, 1);
    l8 += __shfl_xor_sync(0xFFFFFFFFu, l8, 2);
    const float il0 = 1.f / l0, il8 = 1.f / l8;
    #pragma unroll
    for (int ng = 0; ng < 2; ng++) {
        s[ng][0] *= il0; s[ng][1] *= il0;
        s[ng][2] *= il8; s[ng][3] *= il8;
    }

    uint32_t aP[4];
    aP[0] = packh2(s[0][0], s[0][1]);
    aP[1] = packh2(s[0][2], s[0][3]);
    aP[2] = packh2(s[1][0], s[1][1]);
    aP[3] = packh2(s[1][2], s[1][3]);

    float O[4][4];
    #pragma unroll
    for (int i = 0; i < 4; i++)
        #pragma unroll
        for (int c = 0; c < 4; c++) O[i][c] = 0.f;
    #pragma unroll
    for (int dgp = 0; dgp < 2; dgp++) {
        uint32_t bV[4];
        LDSM_X4(bV[0], bV[1], bV[2], bV[3],
                ibase + AI_V + (uint32_t)(dgp * 16 + bnl) * (AI_STRIDE * 2) + bC);
        MMA16816(O[dgp * 2],     aP, bV[0], bV[1]);
        MMA16816(O[dgp * 2 + 1], aP, bV[2], bV[3]);
    }

    __half* ob = att + ((size_t)(bt0 + g8) * NHW + hw0 + w) * 256 + head * 32 + 2 * t4;
    __half* ob8 = ob + (size_t)8 * NHW * 256;
    #pragma unroll
    for (int dg = 0; dg < 4; dg++) {
        *(__half2*)(ob  + dg * 8) = __floats2half2_rn(O[dg][0], O[dg][1]);
        *(__half2*)(ob8 + dg * 8) = __floats2half2_rn(O[dg][2], O[dg][3]);
    }
}

extern "C" void kernel_launch(void* const* d_in, const int* in_sizes, int n_in,
                              void* d_out, int out_size)
{
    const float* x     = (const float*)d_in[0];
    const float* rel   = (const float*)d_in[1];
    const float* w_qkv = (const float*)d_in[2];
    const float* b_qkv = (const float*)d_in[3];
    const float* w_out = (const float*)d_in[4];
    const float* b_out = (const float*)d_in[5];
    float* y = (float*)d_out;

    __half *qkv = nullptr, *att = nullptr, *xh = nullptr, *wh = nullptr;
    cudaGetSymbolAddress((void**)&qkv, g_qkv);
    cudaGetSymbolAddress((void**)&att, g_att);
    cudaGetSymbolAddress((void**)&xh,  g_xh);
    cudaGetSymbolAddress((void**)&wh,  g_wh);

    cudaFuncSetAttribute(gemm_fk_kernel<768, 0>, cudaFuncAttributeMaxDynamicSharedMemorySize, FK_SMEM);
    cudaFuncSetAttribute(gemm_fk_kernel<256, 1>, cudaFuncAttributeMaxDynamicSharedMemorySize, FK_SMEM);
    cudaFuncSetAttribute(attn_mma_kernel, cudaFuncAttributeMaxDynamicSharedMemorySize, ATT_SMEM);

    // Stage 0: fp16 conversions
    cvt_w_kernel<<<(768 + 256) * KDIM / 1024, 256>>>(w_qkv, w_out, wh);
    cvt_x_kernel<<<(int)((size_t)NBT * KDIM * NHW / 1024), 256>>>(x, xh);
    // Stage 1: QKV projection -> qkv fp16 [bt][768][hw]
    gemm_fk_kernel<768, 0><<<dim3(NHW / 128, NBT), 512, FK_SMEM>>>(wh, xh, b_qkv, qkv);
    // Stage 2: temporal attention (tensor-core) -> att fp16 [bt][hw][256]
    attn_mma_kernel<<<dim3(NHW / 16, 8, 4), 512, ATT_SMEM>>>(qkv, rel, att);
    // Stage 3: output projection -> y fp32 [bt][256][hw]
    gemm_fk_kernel<256, 1><<<dim3(NHW / 128, NBT), 512, FK_SMEM>>>(
        wh + (size_t)768 * KDIM, att, b_out, y);
}

// round 12
// speedup vs baseline: 1.2221x; 1.2221x over previous
#include <cuda_runtime.h>
#include <cuda_fp16.h>
#include <cstdint>
#include <math.h>

#define NHW 1024
#define KDIM 256
#define NBT 64

// ---------------- scratch (device globals: allocation-guard-safe) -------------
__device__ __half g_qkv[(size_t)NBT * 768 * NHW];   // 96 MB  [bt][768][hw]
__device__ __half g_att[(size_t)NBT * NHW * 256];   // 32 MB  [bt][hw][256]
__device__ __half g_xh [(size_t)NBT * KDIM * NHW];  // 32 MB  [bt][k][hw]
__device__ __half g_wh [(size_t)(768 + 256) * KDIM];

// ---------------- helpers ------------------------------------------------------
__device__ __forceinline__ uint32_t smem_u32(const void* p) {
    uint32_t a;
    asm("{ .reg .u64 t; cvta.to.shared.u64 t, %1; cvt.u32.u64 %0, t; }" : "=r"(a) : "l"(p));
    return a;
}
__device__ __forceinline__ uint32_t packh2(float lo, float hi) {
    __half2 h = __floats2half2_rn(lo, hi);
    return *reinterpret_cast<uint32_t*>(&h);
}
__device__ __forceinline__ uint32_t prmt(uint32_t a, uint32_t b, uint32_t sel) {
    uint32_t r;
    asm("prmt.b32 %0, %1, %2, %3;" : "=r"(r) : "r"(a), "r"(b), "r"(sel));
    return r;
}
__device__ __forceinline__ void cpa16(uint32_t dst, const void* src) {
    asm volatile("cp.async.cg.shared.global [%0], [%1], 16;" :: "r"(dst), "l"(src));
}
__device__ __forceinline__ void cpa_commit() { asm volatile("cp.async.commit_group;"); }
template<int N> __device__ __forceinline__ void cpa_wait() {
    asm volatile("cp.async.wait_group %0;" :: "n"(N));
}
#define LDSM_X4(r0, r1, r2, r3, addr) \
    asm volatile("ldmatrix.sync.aligned.m8n8.x4.shared.b16 {%0,%1,%2,%3}, [%4];" \
                 : "=r"(r0), "=r"(r1), "=r"(r2), "=r"(r3) : "r"(addr))
#define LDSM_X4_T(r0, r1, r2, r3, addr) \
    asm volatile("ldmatrix.sync.aligned.m8n8.x4.trans.shared.b16 {%0,%1,%2,%3}, [%4];" \
                 : "=r"(r0), "=r"(r1), "=r"(r2), "=r"(r3) : "r"(addr))
#define MMA16816(c, a, b0v, b1v) \
    asm volatile("mma.sync.aligned.m16n8k16.row.col.f32.f16.f16.f32 " \
                 "{%0,%1,%2,%3}, {%4,%5,%6,%7}, {%8,%9}, {%0,%1,%2,%3};" \
                 : "+f"((c)[0]), "+f"((c)[1]), "+f"((c)[2]), "+f"((c)[3]) \
                 : "r"((a)[0]), "r"((a)[1]), "r"((a)[2]), "r"((a)[3]), "r"(b0v), "r"(b1v))

// ---------------- merged convert kernel ----------------------------------------
#define XN ((size_t)NBT * KDIM * NHW)           // 16777216 fp32 -> g_xh
#define WN ((size_t)(768 + 256) * KDIM)         // 262144 fp32  -> g_wh
__global__ __launch_bounds__(256) void cvt_all_kernel(
    const float* __restrict__ x, const float* __restrict__ wq, const float* __restrict__ wo,
    __half* __restrict__ xh, __half* __restrict__ wh)
{
    const size_t i = ((size_t)blockIdx.x * 256 + threadIdx.x) * 4;
    if (i < XN) {
        float4 f = *(const float4*)(x + i);
        uint2 u; u.x = packh2(f.x, f.y); u.y = packh2(f.z, f.w);
        *(uint2*)(xh + i) = u;
    } else {
        const size_t j = i - XN;
        const float* src = (j < (size_t)768 * KDIM) ? (wq + j) : (wo + (j - (size_t)768 * KDIM));
        float4 f = *(const float4*)src;
        uint2 u; u.x = packh2(f.x, f.y); u.y = packh2(f.z, f.w);
        *(uint2*)(wh + j) = u;
    }
}

// ---------------- GEMM: cp.async, B full-K resident, depth-2 chunk stream ------
// C[bt][m][n] = sum_k A[m][k] * B_bt[k][n] + bias[m]
// MODE 0: B src g_xh [bt][k][n]  -> smem [k][n] rows 256B, ldmatrix.trans; out fp16
// MODE 1: B src g_att [bt][n][k] -> smem [n][k] rows 512B, ldmatrix;       out fp32
#define AST 16384
#define SMEM_B_OFF 0
#define SMEM_A_OFF 65536
#define G_SMEM (65536 + 3 * AST)    // 112 KB -> 2 CTA/SM

template<int M, int MODE>
__global__ __launch_bounds__(256, 2) void gemm_async_kernel(
    const __half* __restrict__ A, const __half* __restrict__ B,
    const float* __restrict__ bias, void* __restrict__ outv)
{
    extern __shared__ char smem[];
    const uint32_t sb = smem_u32(smem);

    const int tid  = threadIdx.x;
    const int lane = tid & 31;
    const int wid  = tid >> 5;
    const int wm   = wid >> 2;
    const int wn   = wid & 3;
    const int g8   = lane >> 2;
    const int t4   = lane & 3;

    const int bt = blockIdx.y;
    const int n0 = blockIdx.x * 128;

    constexpr int NC = (M / 128) * 4;    // total A chunks (128 m x 64 k each)

    // stage A chunk c into slot c%3
    auto stage_chunk = [&](int c) {
        const int slot = c % 3;
        const int m0c  = (c >> 2) * 128;
        const int kcc  = c & 3;
        const int m    = tid >> 1;
        const int k16b = (tid & 1) * 4;
        const uint32_t dbase = sb + SMEM_A_OFF + slot * AST + (uint32_t)m * 128u;
        const __half* src = A + (size_t)(m0c + m) * KDIM + kcc * 64;
        #pragma unroll
        for (int q = 0; q < 4; q++) {
            const int k16 = k16b + q;
            cpa16(dbase + (((uint32_t)k16 * 16u) ^ (((uint32_t)m & 7u) << 4)),
                  src + k16 * 8);
        }
    };

    // ---- prologue: B (full K) + chunk0 as group1; chunk1 as group2 ----
    if (MODE == 0) {
        const __half* Bb = B + (size_t)bt * KDIM * NHW;
        const int k = tid;
        const uint32_t dbase = sb + SMEM_B_OFF + (uint32_t)k * 256u;
        const __half* src = Bb + (size_t)k * NHW + n0;
        #pragma unroll
        for (int n16 = 0; n16 < 16; n16++)
            cpa16(dbase + (((uint32_t)n16 * 16u) ^ (((uint32_t)k & 7u) << 4)),
                  src + n16 * 8);
    } else {
        const __half* Bb = B + (size_t)bt * NHW * KDIM;
        const int n = tid >> 1;
        const int kb = (tid & 1) * 16;
        const uint32_t dbase = sb + SMEM_B_OFF + (uint32_t)n * 512u;
        const __half* src = Bb + (size_t)(n0 + n) * KDIM;
        #pragma unroll
        for (int q = 0; q < 16; q++) {
            const int k16 = kb + q;
            cpa16(dbase + (((uint32_t)k16 * 16u) ^ (((uint32_t)n & 7u) << 4)),
                  src + k16 * 8);
        }
    }
    stage_chunk(0); cpa_commit();     // g1 = B + chunk0
    stage_chunk(1); cpa_commit();     // g2 = chunk1

    // fragment lane geometry (proven identities)
    const int am  = ((lane >> 3) & 1) * 8 + (lane & 7);
    const uint32_t aC = ((lane >> 4) & 1) * 16;
    const uint32_t aS = (uint32_t)(am & 7) << 4;
    const int bnl = ((lane >> 4) & 1) * 8 + (lane & 7);
    const uint32_t bC = ((lane >> 3) & 1) * 16;
    const uint32_t bS = (uint32_t)(bnl & 7) << 4;
    const int tk  = lane & 15;
    const int nc8 = ((lane >> 4) & 1) * 8;
    const uint32_t tS = ((uint32_t)lane & 7u) << 4;

    float acc[4][4][4];

    for (int c = 0; c < NC; c++) {
        // retire group of chunk c; pending stays {g(c+1)} (or empty at tail)
        if (c + 1 < NC) cpa_wait<1>(); else cpa_wait<0>();
        __syncthreads();   // data visibility for all threads + slot-(c+2)%3 reuse fence
        if (c + 2 < NC) { stage_chunk(c + 2); cpa_commit(); }

        const int kc = c & 3;
        if (kc == 0) {
            #pragma unroll
            for (int i = 0; i < 4; i++)
                #pragma unroll
                for (int j = 0; j < 4; j++)
                    #pragma unroll
                    for (int q = 0; q < 4; q++) acc[i][j][q] = 0.f;
        }

        const uint32_t abase = sb + SMEM_A_OFF + (uint32_t)(c % 3) * AST;
        #pragma unroll
        for (int kk = 0; kk < 4; kk++) {
            const int kg = kc * 4 + kk;
            uint32_t a[4][4];
            #pragma unroll
            for (int mf = 0; mf < 4; mf++)
                LDSM_X4(a[mf][0], a[mf][1], a[mf][2], a[mf][3],
                        abase + (uint32_t)(wm * 64 + mf * 16 + am) * 128u
                              + (((uint32_t)(kk * 32) + aC) ^ aS));
            uint32_t b[2][4];
            #pragma unroll
            for (int nfp = 0; nfp < 2; nfp++) {
                if (MODE == 0) {
                    LDSM_X4_T(b[nfp][0], b[nfp][1], b[nfp][2], b[nfp][3],
                              sb + SMEM_B_OFF + (uint32_t)((kg * 16 + tk) * 256)
                                 + (((uint32_t)((wn * 32 + nfp * 16 + nc8) * 2)) ^ tS));
                } else {
                    LDSM_X4(b[nfp][0], b[nfp][1], b[nfp][2], b[nfp][3],
                            sb + SMEM_B_OFF + (uint32_t)((wn * 32 + nfp * 16 + bnl) * 512)
                               + (((uint32_t)(kg * 32) + bC) ^ bS));
                }
            }
            #pragma unroll
            for (int mf = 0; mf < 4; mf++)
                #pragma unroll
                for (int nf = 0; nf < 4; nf++)
                    MMA16816(acc[mf][nf], a[mf],
                             b[nf >> 1][(nf & 1) * 2], b[nf >> 1][(nf & 1) * 2 + 1]);
        }

        if (kc == 3) {
            const int m0 = (c >> 2) * 128;
            #pragma unroll
            for (int mf = 0; mf < 4; mf++) {
                const int m = m0 + wm * 64 + mf * 16 + g8;
                const float bz0 = bias[m], bz1 = bias[m + 8];
                #pragma unroll
                for (int nf = 0; nf < 4; nf++) {
                    const int n = n0 + wn * 32 + nf * 8 + 2 * t4;
                    if (MODE == 0) {
                        __half* Oh = (__half*)outv + (size_t)bt * M * NHW;
                        *(__half2*)(Oh + (size_t)m * NHW + n) =
                            __floats2half2_rn(acc[mf][nf][0] + bz0, acc[mf][nf][1] + bz0);
                        *(__half2*)(Oh + (size_t)(m + 8) * NHW + n) =
                            __floats2half2_rn(acc[mf][nf][2] + bz1, acc[mf][nf][3] + bz1);
                    } else {
                        float* Of = (float*)outv + (size_t)bt * M * NHW;
                        *(float2*)(Of + (size_t)m * NHW + n) =
                            make_float2(acc[mf][nf][0] + bz0, acc[mf][nf][1] + bz0);
                        *(float2*)(Of + (size_t)(m + 8) * NHW + n) =
                            make_float2(acc[mf][nf][2] + bz1, acc[mf][nf][3] + bz1);
                    }
                }
            }
        }
    }
}

// ---------------- temporal attention via tensor cores (R9, unchanged) ----------
#define AI_STRIDE 40
#define AI_Q 0
#define AI_K 1280
#define AI_V 2560
#define AI_BYTES 5120
#define ATT_REL_OFF (16 * AI_BYTES)
#define ATT_SMEM (ATT_REL_OFF + 1024)

__device__ __forceinline__ void htr8x8(const uint4* in, uint4* out) {
    const uint32_t* w = (const uint32_t*)in;
    #pragma unroll
    for (int t = 0; t < 8; t++) {
        const uint32_t sel = (t & 1) ? 0x7632u : 0x5410u;
        const int c = t >> 1;
        out[t].x = prmt(w[0 * 4 + c], w[1 * 4 + c], sel);
        out[t].y = prmt(w[2 * 4 + c], w[3 * 4 + c], sel);
        out[t].z = prmt(w[4 * 4 + c], w[5 * 4 + c], sel);
        out[t].w = prmt(w[6 * 4 + c], w[7 * 4 + c], sel);
    }
}

__global__ __launch_bounds__(512, 2) void attn_mma_kernel(
    const __half* __restrict__ qkv, const float* __restrict__ rel,
    __half* __restrict__ att)
{
    extern __shared__ char asmem[];
    const uint32_t sb = smem_u32(asmem);

    const int tid  = threadIdx.x;
    const int hw0  = blockIdx.x * 16;
    const int head = blockIdx.y;
    const int b    = blockIdx.z;
    const int bt0  = b * 16;

    if (tid >= 256) ((float*)(asmem + ATT_REL_OFF))[tid - 256] = rel[head * 256 + tid - 256];

    if (tid < 384) {
        uint4 in[8], out[8];
        if (tid < 256) {
            const int h8 = tid & 1;
            const int d8 = (tid >> 1) & 3;
            const int j  = (tid >> 3) & 15;
            const int tz = tid >> 7;
            const __half* src = qkv + ((size_t)(bt0 + j) * 768 + tz * 256 + head * 32 + d8 * 8) * NHW
                              + hw0 + h8 * 8;
            #pragma unroll
            for (int dd = 0; dd < 8; dd++)
                in[dd] = *(const uint4*)(src + (size_t)dd * NHW);
            htr8x8(in, out);
            const uint32_t dbase = sb + (uint32_t)tz * 1280u + (uint32_t)j * (AI_STRIDE * 2)
                                 + (uint32_t)d8 * 16u + (uint32_t)(h8 * 8) * AI_BYTES;
            #pragma unroll
            for (int t = 0; t < 8; t++)
                *(uint4*)(asmem + (dbase - sb) + (uint32_t)t * AI_BYTES) = out[t];
        } else {
            const int v  = tid - 256;
            const int h8 = v & 1;
            const int j8 = (v >> 1) & 1;
            const int d  = (v >> 2) & 31;
            const __half* src = qkv + ((size_t)(bt0 + j8 * 8) * 768 + 512 + head * 32 + d) * NHW
                              + hw0 + h8 * 8;
            #pragma unroll
            for (int jj = 0; jj < 8; jj++)
                in[jj] = *(const uint4*)(src + (size_t)jj * 768 * NHW);
            htr8x8(in, out);
            const uint32_t dbase = sb + AI_V + (uint32_t)d * (AI_STRIDE * 2)
                                 + (uint32_t)j8 * 16u + (uint32_t)(h8 * 8) * AI_BYTES;
            #pragma unroll
            for (int t = 0; t < 8; t++)
                *(uint4*)(asmem + (dbase - sb) + (uint32_t)t * AI_BYTES) = out[t];
        }
    }
    __syncthreads();

    const int w    = tid >> 5;
    const int lane = tid & 31;
    const int g8   = lane >> 2;
    const int t4   = lane & 3;
    const uint32_t ibase = sb + (uint32_t)w * AI_BYTES;

    const int am  = ((lane >> 3) & 1) * 8 + (lane & 7);
    const uint32_t aC = ((lane >> 4) & 1) * 16;
    const int bnl = ((lane >> 4) & 1) * 8 + (lane & 7);
    const uint32_t bC = ((lane >> 3) & 1) * 16;

    float S[2][4] = {{0.f, 0.f, 0.f, 0.f}, {0.f, 0.f, 0.f, 0.f}};
    #pragma unroll
    for (int kd = 0; kd < 2; kd++) {
        uint32_t aQ[4], bK[4];
        LDSM_X4(aQ[0], aQ[1], aQ[2], aQ[3],
                ibase + AI_Q + (uint32_t)am * (AI_STRIDE * 2) + aC + kd * 32);
        LDSM_X4(bK[0], bK[1], bK[2], bK[3],
                ibase + AI_K + (uint32_t)bnl * (AI_STRIDE * 2) + bC + kd * 32);
        MMA16816(S[0], aQ, bK[0], bK[1]);
        MMA16816(S[1], aQ, bK[2], bK[3]);
    }

    const float scale = 0.1767766952966369f;
    const float* relS = (const float*)(asmem + ATT_REL_OFF);
    float s[2][4];
    #pragma unroll
    for (int ng = 0; ng < 2; ng++)
        #pragma unroll
        for (int q = 0; q < 4; q++) {
            const int row = g8 + (q >= 2 ? 8 : 0);
            const int col = ng * 8 + 2 * t4 + (q & 1);
            s[ng][q] = S[ng][q] * scale + relS[row * 16 + col];
        }
    float mx0 = fmaxf(fmaxf(s[0][0], s[0][1]), fmaxf(s[1][0], s[1][1]));
    float mx8 = fmaxf(fmaxf(s[0][2], s[0][3]), fmaxf(s[1][2], s[1][3]));
    mx0 = fmaxf(mx0, __shfl_xor_sync(0xFFFFFFFFu, mx0, 1));
    mx0 = fmaxf(mx0, __shfl_xor_sync(0xFFFFFFFFu, mx0, 2));
    mx8 = fmaxf(mx8, __shfl_xor_sync(0xFFFFFFFFu, mx8, 1));
    mx8 = fmaxf(mx8, __shfl_xor_sync(0xFFFFFFFFu, mx8, 2));
    #pragma unroll
    for (int ng = 0; ng < 2; ng++) {
        s[ng][0] = __expf(s[ng][0] - mx0);
        s[ng][1] = __expf(s[ng][1] - mx0);
        s[ng][2] = __expf(s[ng][2] - mx8);
        s[ng][3] = __expf(s[ng][3] - mx8);
    }
    float l0 = s[0][0] + s[0][1] + s[1][0] + s[1][1];
    float l8 = s[0][2] + s[0][3] + s[1][2] + s[1][3];
    l0 += __shfl_xor_sync(0xFFFFFFFFu, l0, 1);
    l0 += __shfl_xor_sync(0xFFFFFFFFu, l0, 2);
    l8 += __shfl_xor_sync(0xFFFFFFFFu, l8, 1);
    l8 += __shfl_xor_sync(0xFFFFFFFFu, l8, 2);
    const float il0 = 1.f / l0, il8 = 1.f / l8;
    #pragma unroll
    for (int ng = 0; ng < 2; ng++) {
        s[ng][0] *= il0; s[ng][1] *= il0;
        s[ng][2] *= il8; s[ng][3] *= il8;
    }

    uint32_t aP[4];
    aP[0] = packh2(s[0][0], s[0][1]);
    aP[1] = packh2(s[0][2], s[0][3]);
    aP[2] = packh2(s[1][0], s[1][1]);
    aP[3] = packh2(s[1][2], s[1][3]);

    float O[4][4];
    #pragma unroll
    for (int i = 0; i < 4; i++)
        #pragma unroll
        for (int c = 0; c < 4; c++) O[i][c] = 0.f;
    #pragma unroll
    for (int dgp = 0; dgp < 2; dgp++) {
        uint32_t bV[4];
        LDSM_X4(bV[0], bV[1], bV[2], bV[3],
                ibase + AI_V + (uint32_t)(dgp * 16 + bnl) * (AI_STRIDE * 2) + bC);
        MMA16816(O[dgp * 2],     aP, bV[0], bV[1]);
        MMA16816(O[dgp * 2 + 1], aP, bV[2], bV[3]);
    }

    __half* ob = att + ((size_t)(bt0 + g8) * NHW + hw0 + w) * 256 + head * 32 + 2 * t4;
    __half* ob8 = ob + (size_t)8 * NHW * 256;
    #pragma unroll
    for (int dg = 0; dg < 4; dg++) {
        *(__half2*)(ob  + dg * 8) = __floats2half2_rn(O[dg][0], O[dg][1]);
        *(__half2*)(ob8 + dg * 8) = __floats2half2_rn(O[dg][2], O[dg][3]);
    }
}

extern "C" void kernel_launch(void* const* d_in, const int* in_sizes, int n_in,
                              void* d_out, int out_size)
{
    const float* x     = (const float*)d_in[0];
    const float* rel   = (const float*)d_in[1];
    const float* w_qkv = (const float*)d_in[2];
    const float* b_qkv = (const float*)d_in[3];
    const float* w_out = (const float*)d_in[4];
    const float* b_out = (const float*)d_in[5];
    float* y = (float*)d_out;

    __half *qkv = nullptr, *att = nullptr, *xh = nullptr, *wh = nullptr;
    cudaGetSymbolAddress((void**)&qkv, g_qkv);
    cudaGetSymbolAddress((void**)&att, g_att);
    cudaGetSymbolAddress((void**)&xh,  g_xh);
    cudaGetSymbolAddress((void**)&wh,  g_wh);

    cudaFuncSetAttribute(gemm_async_kernel<768, 0>, cudaFuncAttributeMaxDynamicSharedMemorySize, G_SMEM);
    cudaFuncSetAttribute(gemm_async_kernel<256, 1>, cudaFuncAttributeMaxDynamicSharedMemorySize, G_SMEM);
    cudaFuncSetAttribute(attn_mma_kernel, cudaFuncAttributeMaxDynamicSharedMemorySize, ATT_SMEM);

    // Stage 0: merged fp16 conversion (x + both weight matrices)
    const int cvt_blocks = (int)((XN + WN) / 4 / 256);
    cvt_all_kernel<<<cvt_blocks, 256>>>(x, w_qkv, w_out, xh, wh);
    // Stage 1: QKV projection -> qkv fp16 [bt][768][hw]
    gemm_async_kernel<768, 0><<<dim3(NHW / 128, NBT), 256, G_SMEM>>>(wh, xh, b_qkv, qkv);
    // Stage 2: temporal attention (tensor-core) -> att fp16 [bt][hw][256]
    attn_mma_kernel<<<dim3(NHW / 16, 8, 4), 512, ATT_SMEM>>>(qkv, rel, att);
    // Stage 3: output projection -> y fp32 [bt][256][hw]
    gemm_async_kernel<256, 1><<<dim3(NHW / 128, NBT), 256, G_SMEM>>>(
        wh + (size_t)768 * KDIM, att, b_out, y);
}

// round 16
// speedup vs baseline: 1.2263x; 1.0035x over previous
#include <cuda_runtime.h>
#include <cuda_fp16.h>
#include <cstdint>
#include <math.h>

#define NHW 1024
#define KDIM 256
#define NBT 64

// ---------------- scratch (device globals: allocation-guard-safe) -------------
__device__ __half g_qkv[(size_t)NBT * 768 * NHW];   // 96 MB  [bt][768][hw]
__device__ __half g_att[(size_t)NBT * NHW * 256];   // 32 MB  [bt][hw][256]
__device__ __half g_xh [(size_t)NBT * KDIM * NHW];  // 32 MB  [bt][k][hw]
__device__ __half g_wh [(size_t)(768 + 256) * KDIM];

// ---------------- helpers ------------------------------------------------------
__device__ __forceinline__ uint32_t smem_u32(const void* p) {
    uint32_t a;
    asm("{ .reg .u64 t; cvta.to.shared.u64 t, %1; cvt.u32.u64 %0, t; }" : "=r"(a) : "l"(p));
    return a;
}
__device__ __forceinline__ uint32_t packh2(float lo, float hi) {
    __half2 h = __floats2half2_rn(lo, hi);
    return *reinterpret_cast<uint32_t*>(&h);
}
__device__ __forceinline__ uint32_t prmt(uint32_t a, uint32_t b, uint32_t sel) {
    uint32_t r;
    asm("prmt.b32 %0, %1, %2, %3;" : "=r"(r) : "r"(a), "r"(b), "r"(sel));
    return r;
}
__device__ __forceinline__ void cpa16(uint32_t dst, const void* src) {
    asm volatile("cp.async.cg.shared.global [%0], [%1], 16;" :: "r"(dst), "l"(src));
}
__device__ __forceinline__ void cpa_commit() { asm volatile("cp.async.commit_group;"); }
template<int N> __device__ __forceinline__ void cpa_wait() {
    asm volatile("cp.async.wait_group %0;" :: "n"(N));
}
#define LDSM_X4(r0, r1, r2, r3, addr) \
    asm volatile("ldmatrix.sync.aligned.m8n8.x4.shared.b16 {%0,%1,%2,%3}, [%4];" \
                 : "=r"(r0), "=r"(r1), "=r"(r2), "=r"(r3) : "r"(addr))
#define LDSM_X4_T(r0, r1, r2, r3, addr) \
    asm volatile("ldmatrix.sync.aligned.m8n8.x4.trans.shared.b16 {%0,%1,%2,%3}, [%4];" \
                 : "=r"(r0), "=r"(r1), "=r"(r2), "=r"(r3) : "r"(addr))
#define MMA16816(c, a, b0v, b1v) \
    asm volatile("mma.sync.aligned.m16n8k16.row.col.f32.f16.f16.f32 " \
                 "{%0,%1,%2,%3}, {%4,%5,%6,%7}, {%8,%9}, {%0,%1,%2,%3};" \
                 : "+f"((c)[0]), "+f"((c)[1]), "+f"((c)[2]), "+f"((c)[3]) \
                 : "r"((a)[0]), "r"((a)[1]), "r"((a)[2]), "r"((a)[3]), "r"(b0v), "r"(b1v))

// ---------------- merged convert kernel ----------------------------------------
#define XN ((size_t)NBT * KDIM * NHW)
#define WN ((size_t)(768 + 256) * KDIM)
__global__ __launch_bounds__(256) void cvt_all_kernel(
    const float* __restrict__ x, const float* __restrict__ wq, const float* __restrict__ wo,
    __half* __restrict__ xh, __half* __restrict__ wh)
{
    const size_t i = ((size_t)blockIdx.x * 256 + threadIdx.x) * 4;
    if (i < XN) {
        float4 f = *(const float4*)(x + i);
        uint2 u; u.x = packh2(f.x, f.y); u.y = packh2(f.z, f.w);
        *(uint2*)(xh + i) = u;
    } else {
        const size_t j = i - XN;
        const float* src = (j < (size_t)768 * KDIM) ? (wq + j) : (wo + (j - (size_t)768 * KDIM));
        float4 f = *(const float4*)src;
        uint2 u; u.x = packh2(f.x, f.y); u.y = packh2(f.z, f.w);
        *(uint2*)(wh + j) = u;
    }
}

// ---------------- GEMM: 512 thr, B full-K resident, depth-2 chunk stream -------
// C[bt][m][n] = sum_k A[m][k] * B_bt[k][n] + bias[m]
// warp grid 4x4 over 128x128 tile -> warp tile 32x32, acc 32 regs.
// MODE 0: B src g_xh [bt][k][n]  -> smem [k][n] rows 256B, ldmatrix.trans; out fp16
// MODE 1: B src g_att [bt][n][k] -> smem [n][k] rows 512B, ldmatrix;       out fp32
#define AST 16384
#define SMEM_B_OFF 0
#define SMEM_A_OFF 65536
#define G_SMEM (65536 + 3 * AST)    // 112 KB -> 2 CTA/SM, 32 warps/SM

template<int M, int MODE>
__global__ __launch_bounds__(512, 2) void gemm_async_kernel(
    const __half* __restrict__ A, const __half* __restrict__ B,
    const float* __restrict__ bias, void* __restrict__ outv)
{
    extern __shared__ char smem[];
    const uint32_t sb = smem_u32(smem);

    const int tid  = threadIdx.x;
    const int lane = tid & 31;
    const int wid  = tid >> 5;
    const int wm   = wid >> 2;      // 0..3, 32 m-rows
    const int wn   = wid & 3;       // 0..3, 32 n-cols
    const int g8   = lane >> 2;
    const int t4   = lane & 3;

    const int bt = blockIdx.y;
    const int n0 = blockIdx.x * 128;

    constexpr int NC = (M / 128) * 4;

    // stage A chunk c (128 m x 64 k, 16KB) into slot c%3; 2 cpa16/thread
    auto stage_chunk = [&](int c) {
        const int slot = c % 3;
        const int m0c  = (c >> 2) * 128;
        const int kcc  = c & 3;
        const int m    = tid >> 2;          // 0..127
        const int k16b = (tid & 3) * 2;
        const uint32_t dbase = sb + SMEM_A_OFF + slot * AST + (uint32_t)m * 128u;
        const __half* src = A + (size_t)(m0c + m) * KDIM + kcc * 64;
        #pragma unroll
        for (int q = 0; q < 2; q++) {
            const int k16 = k16b + q;
            cpa16(dbase + (((uint32_t)k16 * 16u) ^ (((uint32_t)m & 7u) << 4)),
                  src + k16 * 8);
        }
    };

    // ---- prologue: B full-K + chunk0 (g1); chunk1 (g2) ----
    if (MODE == 0) {
        const __half* Bb = B + (size_t)bt * KDIM * NHW;
        const int k = tid >> 1;             // 0..255
        const int n16b = (tid & 1) * 8;
        const uint32_t dbase = sb + SMEM_B_OFF + (uint32_t)k * 256u;
        const __half* src = Bb + (size_t)k * NHW + n0;
        #pragma unroll
        for (int q = 0; q < 8; q++) {
            const int n16 = n16b + q;
            cpa16(dbase + (((uint32_t)n16 * 16u) ^ (((uint32_t)k & 7u) << 4)),
                  src + n16 * 8);
        }
    } else {
        const __half* Bb = B + (size_t)bt * NHW * KDIM;
        const int n = tid >> 2;             // 0..127
        const int kb = (tid & 3) * 8;
        const uint32_t dbase = sb + SMEM_B_OFF + (uint32_t)n * 512u;
        const __half* src = Bb + (size_t)(n0 + n) * KDIM;
        #pragma unroll
        for (int q = 0; q < 8; q++) {
            const int k16 = kb + q;
            cpa16(dbase + (((uint32_t)k16 * 16u) ^ (((uint32_t)n & 7u) << 4)),
                  src + k16 * 8);
        }
    }
    stage_chunk(0); cpa_commit();     // g1 = B + chunk0
    stage_chunk(1); cpa_commit();     // g2 = chunk1

    // fragment lane geometry (proven identities)
    const int am  = ((lane >> 3) & 1) * 8 + (lane & 7);
    const uint32_t aC = ((lane >> 4) & 1) * 16;
    const uint32_t aS = (uint32_t)(am & 7) << 4;
    const int bnl = ((lane >> 4) & 1) * 8 + (lane & 7);
    const uint32_t bC = ((lane >> 3) & 1) * 16;
    const uint32_t bS = (uint32_t)(bnl & 7) << 4;
    const int tk  = lane & 15;
    const int nc8 = ((lane >> 4) & 1) * 8;
    const uint32_t tS = ((uint32_t)lane & 7u) << 4;

    float acc[2][4][4];

    for (int c = 0; c < NC; c++) {
        if (c + 1 < NC) cpa_wait<1>(); else cpa_wait<0>();
        __syncthreads();
        if (c + 2 < NC) { stage_chunk(c + 2); cpa_commit(); }

        const int kc = c & 3;
        if (kc == 0) {
            #pragma unroll
            for (int i = 0; i < 2; i++)
                #pragma unroll
                for (int j = 0; j < 4; j++)
                    #pragma unroll
                    for (int q = 0; q < 4; q++) acc[i][j][q] = 0.f;
        }

        const uint32_t abase = sb + SMEM_A_OFF + (uint32_t)(c % 3) * AST;
        #pragma unroll
        for (int kk = 0; kk < 4; kk++) {
            const int kg = kc * 4 + kk;
            uint32_t a[2][4];
            #pragma unroll
            for (int mf = 0; mf < 2; mf++)
                LDSM_X4(a[mf][0], a[mf][1], a[mf][2], a[mf][3],
                        abase + (uint32_t)(wm * 32 + mf * 16 + am) * 128u
                              + (((uint32_t)(kk * 32) + aC) ^ aS));
            uint32_t b[2][4];
            #pragma unroll
            for (int nfp = 0; nfp < 2; nfp++) {
                if (MODE == 0) {
                    LDSM_X4_T(b[nfp][0], b[nfp][1], b[nfp][2], b[nfp][3],
                              sb + SMEM_B_OFF + (uint32_t)((kg * 16 + tk) * 256)
                                 + (((uint32_t)((wn * 32 + nfp * 16 + nc8) * 2)) ^ tS));
                } else {
                    LDSM_X4(b[nfp][0], b[nfp][1], b[nfp][2], b[nfp][3],
                            sb + SMEM_B_OFF + (uint32_t)((wn * 32 + nfp * 16 + bnl) * 512)
                               + (((uint32_t)(kg * 32) + bC) ^ bS));
                }
            }
            #pragma unroll
            for (int mf = 0; mf < 2; mf++)
                #pragma unroll
                for (int nf = 0; nf < 4; nf++)
                    MMA16816(acc[mf][nf], a[mf],
                             b[nf >> 1][(nf & 1) * 2], b[nf >> 1][(nf & 1) * 2 + 1]);
        }

        if (kc == 3) {
            const int m0 = (c >> 2) * 128;
            #pragma unroll
            for (int mf = 0; mf < 2; mf++) {
                const int m = m0 + wm * 32 + mf * 16 + g8;
                const float bz0 = bias[m], bz1 = bias[m + 8];
                #pragma unroll
                for (int nf = 0; nf < 4; nf++) {
                    const int n = n0 + wn * 32 + nf * 8 + 2 * t4;
                    if (MODE == 0) {
                        __half* Oh = (__half*)outv + (size_t)bt * M * NHW;
                        *(__half2*)(Oh + (size_t)m * NHW + n) =
                            __floats2half2_rn(acc[mf][nf][0] + bz0, acc[mf][nf][1] + bz0);
                        *(__half2*)(Oh + (size_t)(m + 8) * NHW + n) =
                            __floats2half2_rn(acc[mf][nf][2] + bz1, acc[mf][nf][3] + bz1);
                    } else {
                        float* Of = (float*)outv + (size_t)bt * M * NHW;
                        *(float2*)(Of + (size_t)m * NHW + n) =
                            make_float2(acc[mf][nf][0] + bz0, acc[mf][nf][1] + bz0);
                        *(float2*)(Of + (size_t)(m + 8) * NHW + n) =
                            make_float2(acc[mf][nf][2] + bz1, acc[mf][nf][3] + bz1);
                    }
                }
            }
        }
    }
}

// ---------------- temporal attention via tensor cores (R9, unchanged) ----------
#define AI_STRIDE 40
#define AI_Q 0
#define AI_K 1280
#define AI_V 2560
#define AI_BYTES 5120
#define ATT_REL_OFF (16 * AI_BYTES)
#define ATT_SMEM (ATT_REL_OFF + 1024)

__device__ __forceinline__ void htr8x8(const uint4* in, uint4* out) {
    const uint32_t* w = (const uint32_t*)in;
    #pragma unroll
    for (int t = 0; t < 8; t++) {
        const uint32_t sel = (t & 1) ? 0x7632u : 0x5410u;
        const int c = t >> 1;
        out[t].x = prmt(w[0 * 4 + c], w[1 * 4 + c], sel);
        out[t].y = prmt(w[2 * 4 + c], w[3 * 4 + c], sel);
        out[t].z = prmt(w[4 * 4 + c], w[5 * 4 + c], sel);
        out[t].w = prmt(w[6 * 4 + c], w[7 * 4 + c], sel);
    }
}

__global__ __launch_bounds__(512, 2) void attn_mma_kernel(
    const __half* __restrict__ qkv, const float* __restrict__ rel,
    __half* __restrict__ att)
{
    extern __shared__ char asmem[];
    const uint32_t sb = smem_u32(asmem);

    const int tid  = threadIdx.x;
    const int hw0  = blockIdx.x * 16;
    const int head = blockIdx.y;
    const int b    = blockIdx.z;
    const int bt0  = b * 16;

    if (tid >= 256) ((float*)(asmem + ATT_REL_OFF))[tid - 256] = rel[head * 256 + tid - 256];

    if (tid < 384) {
        uint4 in[8], out[8];
        if (tid < 256) {
            const int h8 = tid & 1;
            const int d8 = (tid >> 1) & 3;
            const int j  = (tid >> 3) & 15;
            const int tz = tid >> 7;
            const __half* src = qkv + ((size_t)(bt0 + j) * 768 + tz * 256 + head * 32 + d8 * 8) * NHW
                              + hw0 + h8 * 8;
            #pragma unroll
            for (int dd = 0; dd < 8; dd++)
                in[dd] = *(const uint4*)(src + (size_t)dd * NHW);
            htr8x8(in, out);
            const uint32_t dbase = sb + (uint32_t)tz * 1280u + (uint32_t)j * (AI_STRIDE * 2)
                                 + (uint32_t)d8 * 16u + (uint32_t)(h8 * 8) * AI_BYTES;
            #pragma unroll
            for (int t = 0; t < 8; t++)
                *(uint4*)(asmem + (dbase - sb) + (uint32_t)t * AI_BYTES) = out[t];
        } else {
            const int v  = tid - 256;
            const int h8 = v & 1;
            const int j8 = (v >> 1) & 1;
            const int d  = (v >> 2) & 31;
            const __half* src = qkv + ((size_t)(bt0 + j8 * 8) * 768 + 512 + head * 32 + d) * NHW
                              + hw0 + h8 * 8;
            #pragma unroll
            for (int jj = 0; jj < 8; jj++)
                in[jj] = *(const uint4*)(src + (size_t)jj * 768 * NHW);
            htr8x8(in, out);
            const uint32_t dbase = sb + AI_V + (uint32_t)d * (AI_STRIDE * 2)
                                 + (uint32_t)j8 * 16u + (uint32_t)(h8 * 8) * AI_BYTES;
            #pragma unroll
            for (int t = 0; t < 8; t++)
                *(uint4*)(asmem + (dbase - sb) + (uint32_t)t * AI_BYTES) = out[t];
        }
    }
    __syncthreads();

    const int w    = tid >> 5;
    const int lane = tid & 31;
    const int g8   = lane >> 2;
    const int t4   = lane & 3;
    const uint32_t ibase = sb + (uint32_t)w * AI_BYTES;

    const int am  = ((lane >> 3) & 1) * 8 + (lane & 7);
    const uint32_t aC = ((lane >> 4) & 1) * 16;
    const int bnl = ((lane >> 4) & 1) * 8 + (lane & 7);
    const uint32_t bC = ((lane >> 3) & 1) * 16;

    float S[2][4] = {{0.f, 0.f, 0.f, 0.f}, {0.f, 0.f, 0.f, 0.f}};
    #pragma unroll
    for (int kd = 0; kd < 2; kd++) {
        uint32_t aQ[4], bK[4];
        LDSM_X4(aQ[0], aQ[1], aQ[2], aQ[3],
                ibase + AI_Q + (uint32_t)am * (AI_STRIDE * 2) + aC + kd * 32);
        LDSM_X4(bK[0], bK[1], bK[2], bK[3],
                ibase + AI_K + (uint32_t)bnl * (AI_STRIDE * 2) + bC + kd * 32);
        MMA16816(S[0], aQ, bK[0], bK[1]);
        MMA16816(S[1], aQ, bK[2], bK[3]);
    }

    const float scale = 0.1767766952966369f;
    const float* relS = (const float*)(asmem + ATT_REL_OFF);
    float s[2][4];
    #pragma unroll
    for (int ng = 0; ng < 2; ng++)
        #pragma unroll
        for (int q = 0; q < 4; q++) {
            const int row = g8 + (q >= 2 ? 8 : 0);
            const int col = ng * 8 + 2 * t4 + (q & 1);
            s[ng][q] = S[ng][q] * scale + relS[row * 16 + col];
        }
    float mx0 = fmaxf(fmaxf(s[0][0], s[0][1]), fmaxf(s[1][0], s[1][1]));
    float mx8 = fmaxf(fmaxf(s[0][2], s[0][3]), fmaxf(s[1][2], s[1][3]));
    mx0 = fmaxf(mx0, __shfl_xor_sync(0xFFFFFFFFu, mx0, 1));
    mx0 = fmaxf(mx0, __shfl_xor_sync(0xFFFFFFFFu, mx0, 2));
    mx8 = fmaxf(mx8, __shfl_xor_sync(0xFFFFFFFFu, mx8, 1));
    mx8 = fmaxf(mx8, __shfl_xor_sync(0xFFFFFFFFu, mx8, 2));
    #pragma unroll
    for (int ng = 0; ng < 2; ng++) {
        s[ng][0] = __expf(s[ng][0] - mx0);
        s[ng][1] = __expf(s[ng][1] - mx0);
        s[ng][2] = __expf(s[ng][2] - mx8);
        s[ng][3] = __expf(s[ng][3] - mx8);
    }
    float l0 = s[0][0] + s[0][1] + s[1][0] + s[1][1];
    float l8 = s[0][2] + s[0][3] + s[1][2] + s[1][3];
    l0 += __shfl_xor_sync(0xFFFFFFFFu, l0, 1);
    l0 += __shfl_xor_sync(0xFFFFFFFFu, l0, 2);
    l8 += __shfl_xor_sync(0xFFFFFFFFu, l8, 1);
    l8 += __shfl_xor_sync(0xFFFFFFFFu, l8, 2);
    const float il0 = 1.f / l0, il8 = 1.f / l8;
    #pragma unroll
    for (int ng = 0; ng < 2; ng++) {
        s[ng][0] *= il0; s[ng][1] *= il0;
        s[ng][2] *= il8; s[ng][3] *= il8;
    }

    uint32_t aP[4];
    aP[0] = packh2(s[0][0], s[0][1]);
    aP[1] = packh2(s[0][2], s[0][3]);
    aP[2] = packh2(s[1][0], s[1][1]);
    aP[3] = packh2(s[1][2], s[1][3]);

    float O[4][4];
    #pragma unroll
    for (int i = 0; i < 4; i++)
        #pragma unroll
        for (int c = 0; c < 4; c++) O[i][c] = 0.f;
    #pragma unroll
    for (int dgp = 0; dgp < 2; dgp++) {
        uint32_t bV[4];
        LDSM_X4(bV[0], bV[1], bV[2], bV[3],
                ibase + AI_V + (uint32_t)(dgp * 16 + bnl) * (AI_STRIDE * 2) + bC);
        MMA16816(O[dgp * 2],     aP, bV[0], bV[1]);
        MMA16816(O[dgp * 2 + 1], aP, bV[2], bV[3]);
    }

    __half* ob = att + ((size_t)(bt0 + g8) * NHW + hw0 + w) * 256 + head * 32 + 2 * t4;
    __half* ob8 = ob + (size_t)8 * NHW * 256;
    #pragma unroll
    for (int dg = 0; dg < 4; dg++) {
        *(__half2*)(ob  + dg * 8) = __floats2half2_rn(O[dg][0], O[dg][1]);
        *(__half2*)(ob8 + dg * 8) = __floats2half2_rn(O[dg][2], O[dg][3]);
    }
}

extern "C" void kernel_launch(void* const* d_in, const int* in_sizes, int n_in,
                              void* d_out, int out_size)
{
    const float* x     = (const float*)d_in[0];
    const float* rel   = (const float*)d_in[1];
    const float* w_qkv = (const float*)d_in[2];
    const float* b_qkv = (const float*)d_in[3];
    const float* w_out = (const float*)d_in[4];
    const float* b_out = (const float*)d_in[5];
    float* y = (float*)d_out;

    __half *qkv = nullptr, *att = nullptr, *xh = nullptr, *wh = nullptr;
    cudaGetSymbolAddress((void**)&qkv, g_qkv);
    cudaGetSymbolAddress((void**)&att, g_att);
    cudaGetSymbolAddress((void**)&xh,  g_xh);
    cudaGetSymbolAddress((void**)&wh,  g_wh);

    cudaFuncSetAttribute(gemm_async_kernel<768, 0>, cudaFuncAttributeMaxDynamicSharedMemorySize, G_SMEM);
    cudaFuncSetAttribute(gemm_async_kernel<256, 1>, cudaFuncAttributeMaxDynamicSharedMemorySize, G_SMEM);
    cudaFuncSetAttribute(attn_mma_kernel, cudaFuncAttributeMaxDynamicSharedMemorySize, ATT_SMEM);

    // Stage 0: merged fp16 conversion (x + both weight matrices)
    const int cvt_blocks = (int)((XN + WN) / 4 / 256);
    cvt_all_kernel<<<cvt_blocks, 256>>>(x, w_qkv, w_out, xh, wh);
    // Stage 1: QKV projection -> qkv fp16 [bt][768][hw]
    gemm_async_kernel<768, 0><<<dim3(NHW / 128, NBT), 512, G_SMEM>>>(wh, xh, b_qkv, qkv);
    // Stage 2: temporal attention (tensor-core) -> att fp16 [bt][hw][256]
    attn_mma_kernel<<<dim3(NHW / 16, 8, 4), 512, ATT_SMEM>>>(qkv, rel, att);
    // Stage 3: output projection -> y fp32 [bt][256][hw]
    gemm_async_kernel<256, 1><<<dim3(NHW / 128, NBT), 512, G_SMEM>>>(
        wh + (size_t)768 * KDIM, att, b_out, y);
}